// round 2
// baseline (speedup 1.0000x reference)
#include <cuda_runtime.h>

// NeuralBPDecoder: sparse BP, single persistent kernel.
// 148 blocks x 1024 threads (guaranteed co-resident, 1 block/SM),
// software grid barrier between phases:
//   zero counters -> stream H (537MB, __ldcs) building ELL adjacency ->
//   sort lists (determinism) + transpose inputs -> 15x (v->c, c->v) -> output.
// State is node-major (node, batch) so every edge gather is one 128B line;
// warps process 4 edges at a time as 4 groups x 8 lanes x float4.

#define NC 8192
#define NV 16384
#define NB 32
#define RD 64      // max row degree (Poisson ~16.4)
#define CD 48      // max col degree (Poisson ~8.2)
#define ITERS 15
#define NBLK 148
#define NTHR 1024
#define NWARP ((NBLK * NTHR) / 32)   // 4736

__device__ int   g_row_cnt[NC];
__device__ int   g_row_cols[NC * RD];
__device__ int   g_col_cnt[NV];
__device__ int   g_col_rows[NV * CD];
__device__ float g_vT[NV * NB];
__device__ float g_cT[NC * NB];
__device__ float g_sT[NC * NB];
__device__ float g_llrT[NV * NB];

__device__ unsigned g_bar_arrive;   // zero-init; returns to 0 every barrier
__device__ unsigned g_bar_gen;      // monotonically increasing generation

__device__ __forceinline__ void grid_sync() {
    __syncthreads();
    if (threadIdx.x == 0) {
        __threadfence();
        volatile unsigned* genp = &g_bar_gen;
        unsigned gen = *genp;
        if (atomicAdd(&g_bar_arrive, 1) == NBLK - 1) {
            g_bar_arrive = 0;
            __threadfence();
            atomicAdd(&g_bar_gen, 1);
        } else {
            while (*genp == gen) { }
        }
        __threadfence();
    }
    __syncthreads();
}

__global__ void __launch_bounds__(NTHR, 1)
bp_mega(const float* __restrict__ synd, const float* __restrict__ H,
        const float* __restrict__ llr,  const float* __restrict__ wvc_p,
        const float* __restrict__ wcv_p, const float* __restrict__ damp_p,
        float* __restrict__ out) {
    const int tid   = blockIdx.x * NTHR + threadIdx.x;
    const int gsz   = NBLK * NTHR;
    const int wid   = tid >> 5;
    const int lane  = tid & 31;
    const int sub   = lane & 7;      // float4 slot within the 32-batch row
    const int grp   = lane >> 3;     // which of 4 simultaneous edges

    const float wvc  = __ldg(wvc_p);
    const float wcv  = __ldg(wcv_p);
    const float damp = __ldg(damp_p);

    float4* __restrict__ vT4   = (float4*)g_vT;
    float4* __restrict__ cT4   = (float4*)g_cT;
    float4* __restrict__ sT4   = (float4*)g_sT;
    float4* __restrict__ llrT4 = (float4*)g_llrT;

    // ---- Phase 0: zero degree counters ----
    for (int i = tid; i < NV; i += gsz) {
        g_col_cnt[i] = 0;
        if (i < NC) g_row_cnt[i] = 0;
    }
    grid_sync();

    // ---- Phase 1: stream H, build adjacency ----
    {
        const float4* H4 = (const float4*)H;
        const long n4 = (long)NC * NV / 4;
        for (long i = tid; i < n4; i += gsz) {
            float4 h = __ldcs(&H4[i]);
            if (h.x == 0.0f && h.y == 0.0f && h.z == 0.0f && h.w == 0.0f)
                continue;
            long base = i * 4;
            float vals[4] = {h.x, h.y, h.z, h.w};
            #pragma unroll
            for (int k = 0; k < 4; k++) {
                if (vals[k] != 0.0f) {
                    long e = base + k;
                    int c = (int)(e >> 14);
                    int v = (int)(e & (NV - 1));
                    int rs = atomicAdd(&g_row_cnt[c], 1);
                    if (rs < RD) g_row_cols[c * RD + rs] = v;
                    int cs = atomicAdd(&g_col_cnt[v], 1);
                    if (cs < CD) g_col_rows[v * CD + cs] = c;
                }
            }
        }
    }
    grid_sync();

    // ---- Phase 2: sort adjacency (determinism) + transpose inputs ----
    for (int i = tid; i < NV; i += gsz) {
        {
            int n = min(g_col_cnt[i], CD);
            g_col_cnt[i] = n;
            int* a = &g_col_rows[i * CD];
            for (int j = 1; j < n; j++) {
                int key = a[j]; int k = j - 1;
                while (k >= 0 && a[k] > key) { a[k + 1] = a[k]; k--; }
                a[k + 1] = key;
            }
        }
        if (i < NC) {
            int n = min(g_row_cnt[i], RD);
            g_row_cnt[i] = n;
            int* a = &g_row_cols[i * RD];
            for (int j = 1; j < n; j++) {
                int key = a[j]; int k = j - 1;
                while (k >= 0 && a[k] > key) { a[k + 1] = a[k]; k--; }
                a[k + 1] = key;
            }
        }
    }
    // coalesced reads, scattered (L2) writes
    for (int i = tid; i < NB * NV; i += gsz) {
        int b = i >> 14, v = i & (NV - 1);
        float x = llr[i];
        g_llrT[(v << 5) + b] = x;
        g_vT[(v << 5) + b]   = x;
    }
    for (int i = tid; i < NB * NC; i += gsz) {
        int b = i >> 13, c = i & (NC - 1);
        g_sT[(c << 5) + b] = 1.0f - 2.0f * synd[i];
    }
    grid_sync();

    // ---- Phase 3: BP iterations ----
    for (int it = 0; it < ITERS; it++) {
        // v -> c : one warp per check, 4 edges per pass
        for (int c = wid; c < NC; c += NWARP) {
            int deg = g_row_cnt[c];
            const int* __restrict__ cols = &g_row_cols[c * RD];
            float4 acc = make_float4(0.f, 0.f, 0.f, 0.f);
            for (int j = 0; j < deg; j += 4) {
                int e = j + grp;
                if (e < deg) {
                    float4 a = vT4[(cols[e] << 3) + sub];
                    acc.x += a.x; acc.y += a.y; acc.z += a.z; acc.w += a.w;
                }
            }
            // combine the 4 edge-groups (fixed per-lane order -> deterministic)
            #pragma unroll
            for (int ofs = 8; ofs <= 16; ofs <<= 1) {
                acc.x += __shfl_xor_sync(0xffffffffu, acc.x, ofs);
                acc.y += __shfl_xor_sync(0xffffffffu, acc.y, ofs);
                acc.z += __shfl_xor_sync(0xffffffffu, acc.z, ofs);
                acc.w += __shfl_xor_sync(0xffffffffu, acc.w, ofs);
            }
            if (lane < 8) {
                float4 s = sT4[(c << 3) + sub];
                float4 m;
                m.x = s.x * tanhf(0.5f * wvc * acc.x);
                m.y = s.y * tanhf(0.5f * wvc * acc.y);
                m.z = s.z * tanhf(0.5f * wvc * acc.z);
                m.w = s.w * tanhf(0.5f * wvc * acc.w);
                cT4[(c << 3) + sub] = m;
            }
        }
        grid_sync();

        // c -> v + damped update : one warp per var
        for (int v = wid; v < NV; v += NWARP) {
            int deg = g_col_cnt[v];
            const int* __restrict__ rows = &g_col_rows[v * CD];
            float4 acc = make_float4(0.f, 0.f, 0.f, 0.f);
            for (int j = 0; j < deg; j += 4) {
                int e = j + grp;
                if (e < deg) {
                    float4 a = cT4[(rows[e] << 3) + sub];
                    acc.x += a.x; acc.y += a.y; acc.z += a.z; acc.w += a.w;
                }
            }
            #pragma unroll
            for (int ofs = 8; ofs <= 16; ofs <<= 1) {
                acc.x += __shfl_xor_sync(0xffffffffu, acc.x, ofs);
                acc.y += __shfl_xor_sync(0xffffffffu, acc.y, ofs);
                acc.z += __shfl_xor_sync(0xffffffffu, acc.z, ofs);
                acc.w += __shfl_xor_sync(0xffffffffu, acc.w, ofs);
            }
            if (lane < 8) {
                int idx = (v << 3) + sub;
                float4 vb = vT4[idx];
                float4 ch = llrT4[idx];
                float om = 1.0f - damp;
                vb.x = damp * vb.x + om * (ch.x + wcv * acc.x);
                vb.y = damp * vb.y + om * (ch.y + wcv * acc.y);
                vb.z = damp * vb.z + om * (ch.z + wcv * acc.z);
                vb.w = damp * vb.w + om * (ch.w + wcv * acc.w);
                vT4[idx] = vb;
            }
        }
        grid_sync();
    }

    // ---- Phase 4: output sigmoid(-v) in (b, v) order ----
    for (int i = tid; i < NB * NV; i += gsz) {
        int b = i >> 14, v = i & (NV - 1);
        float x = g_vT[(v << 5) + b];
        out[i] = 1.0f / (1.0f + expf(x));
    }
}

extern "C" void kernel_launch(void* const* d_in, const int* in_sizes, int n_in,
                              void* d_out, int out_size) {
    const float* synd = (const float*)d_in[0];
    const float* H    = (const float*)d_in[1];
    const float* llr  = (const float*)d_in[2];
    const float* wvc  = (const float*)d_in[3];
    const float* wcv  = (const float*)d_in[4];
    const float* damp = (const float*)d_in[5];
    float* out = (float*)d_out;

    bp_mega<<<NBLK, NTHR>>>(synd, H, llr, wvc, wcv, damp, out);
}

// round 3
// speedup vs baseline: 1.1627x; 1.1627x over previous
#include <cuda_runtime.h>

// NeuralBPDecoder: sparse BP.
// 3 launches: zero counters -> build ELL adjacency (deep-batched H scan,
// bandwidth-bound) -> persistent kernel (sort + transpose + 15 BP iterations
// with software grid barrier + output).

#define NC 8192
#define NV 16384
#define NB 32
#define RD 64
#define CD 48
#define ITERS 15
#define NBLK 148
#define NTHR 1024
#define NWARP ((NBLK * NTHR) / 32)

#define B_BLOCKS 2048
#define B_THREADS 256
#define U 8

__device__ int   g_row_cnt[NC];
__device__ int   g_row_cols[NC * RD];
__device__ int   g_col_cnt[NV];
__device__ int   g_col_rows[NV * CD];
__device__ float g_vT[NV * NB];
__device__ float g_cT[NC * NB];
__device__ float g_sT[NC * NB];
__device__ float g_llrT[NV * NB];

__device__ unsigned g_bar_arrive;
__device__ unsigned g_bar_gen;

__device__ __forceinline__ void grid_sync() {
    __syncthreads();
    if (threadIdx.x == 0) {
        __threadfence();
        volatile unsigned* genp = &g_bar_gen;
        unsigned gen = *genp;
        if (atomicAdd(&g_bar_arrive, 1) == NBLK - 1) {
            g_bar_arrive = 0;
            __threadfence();
            atomicAdd(&g_bar_gen, 1);
        } else {
            while (*genp == gen) { }
        }
        __threadfence();
    }
    __syncthreads();
}

__global__ void k_zero() {
    int i = blockIdx.x * blockDim.x + threadIdx.x;
    if (i < NV) g_col_cnt[i] = 0;
    if (i < NC) g_row_cnt[i] = 0;
}

__device__ __forceinline__ void emit_quad(long i, uint4 h) {
    long base = i * 4;
    unsigned vals[4] = {h.x, h.y, h.z, h.w};
    #pragma unroll
    for (int k = 0; k < 4; k++) {
        if (vals[k]) {
            long e = base + k;
            int c = (int)(e >> 14);
            int v = (int)(e & (NV - 1));
            int rs = atomicAdd(&g_row_cnt[c], 1);
            if (rs < RD) g_row_cols[c * RD + rs] = v;
            int cs = atomicAdd(&g_col_cnt[v], 1);
            if (cs < CD) g_col_rows[v * CD + cs] = c;
        }
    }
}

// Stream H (537 MB) with 8 independent in-flight loads per thread.
__global__ void __launch_bounds__(B_THREADS)
k_build(const uint4* __restrict__ H4) {
    const long n4 = (long)NC * NV / 4;
    const long stride = (long)B_BLOCKS * B_THREADS;
    long i = (long)blockIdx.x * B_THREADS + threadIdx.x;

    for (; i + (U - 1) * stride < n4; i += U * stride) {
        uint4 h[U];
        #pragma unroll
        for (int u = 0; u < U; u++)
            h[u] = __ldcs(&H4[i + u * stride]);
        #pragma unroll
        for (int u = 0; u < U; u++) {
            if (h[u].x | h[u].y | h[u].z | h[u].w)
                emit_quad(i + u * stride, h[u]);
        }
    }
    for (; i < n4; i += stride) {
        uint4 h = __ldcs(&H4[i]);
        if (h.x | h.y | h.z | h.w)
            emit_quad(i, h);
    }
}

__global__ void __launch_bounds__(NTHR, 1)
bp_persist(const float* __restrict__ synd, const float* __restrict__ llr,
           const float* __restrict__ wvc_p, const float* __restrict__ wcv_p,
           const float* __restrict__ damp_p, float* __restrict__ out) {
    const int tid  = blockIdx.x * NTHR + threadIdx.x;
    const int gsz  = NBLK * NTHR;
    const int wid  = tid >> 5;
    const int lane = tid & 31;
    const int sub  = lane & 7;   // float4 slot within 32-batch row
    const int grp  = lane >> 3;  // 4 edges processed simultaneously

    const float wvc  = __ldg(wvc_p);
    const float wcv  = __ldg(wcv_p);
    const float damp = __ldg(damp_p);

    float4* __restrict__ vT4   = (float4*)g_vT;
    float4* __restrict__ cT4   = (float4*)g_cT;
    float4* __restrict__ sT4   = (float4*)g_sT;
    float4* __restrict__ llrT4 = (float4*)g_llrT;

    // ---- sort adjacency (deterministic sum order) + transpose inputs ----
    for (int i = tid; i < NV; i += gsz) {
        {
            int n = min(g_col_cnt[i], CD);
            g_col_cnt[i] = n;
            int* a = &g_col_rows[i * CD];
            for (int j = 1; j < n; j++) {
                int key = a[j]; int k = j - 1;
                while (k >= 0 && a[k] > key) { a[k + 1] = a[k]; k--; }
                a[k + 1] = key;
            }
        }
        if (i < NC) {
            int n = min(g_row_cnt[i], RD);
            g_row_cnt[i] = n;
            int* a = &g_row_cols[i * RD];
            for (int j = 1; j < n; j++) {
                int key = a[j]; int k = j - 1;
                while (k >= 0 && a[k] > key) { a[k + 1] = a[k]; k--; }
                a[k + 1] = key;
            }
        }
    }
    for (int i = tid; i < NB * NV; i += gsz) {
        int b = i >> 14, v = i & (NV - 1);
        float x = llr[i];
        g_llrT[(v << 5) + b] = x;
        g_vT[(v << 5) + b]   = x;
    }
    for (int i = tid; i < NB * NC; i += gsz) {
        int b = i >> 13, c = i & (NC - 1);
        g_sT[(c << 5) + b] = 1.0f - 2.0f * synd[i];
    }
    grid_sync();

    // ---- BP iterations ----
    for (int it = 0; it < ITERS; it++) {
        // v -> c : one warp per check, 4 edges/pass (4 groups x 8 lanes x float4)
        for (int c = wid; c < NC; c += NWARP) {
            int deg = g_row_cnt[c];
            const int* __restrict__ cols = &g_row_cols[c * RD];
            float4 acc = make_float4(0.f, 0.f, 0.f, 0.f);
            for (int j = 0; j < deg; j += 4) {
                int e = j + grp;
                if (e < deg) {
                    float4 a = vT4[(cols[e] << 3) + sub];
                    acc.x += a.x; acc.y += a.y; acc.z += a.z; acc.w += a.w;
                }
            }
            #pragma unroll
            for (int ofs = 8; ofs <= 16; ofs <<= 1) {
                acc.x += __shfl_xor_sync(0xffffffffu, acc.x, ofs);
                acc.y += __shfl_xor_sync(0xffffffffu, acc.y, ofs);
                acc.z += __shfl_xor_sync(0xffffffffu, acc.z, ofs);
                acc.w += __shfl_xor_sync(0xffffffffu, acc.w, ofs);
            }
            if (lane < 8) {
                float4 s = sT4[(c << 3) + sub];
                float4 m;
                m.x = s.x * tanhf(0.5f * wvc * acc.x);
                m.y = s.y * tanhf(0.5f * wvc * acc.y);
                m.z = s.z * tanhf(0.5f * wvc * acc.z);
                m.w = s.w * tanhf(0.5f * wvc * acc.w);
                cT4[(c << 3) + sub] = m;
            }
        }
        grid_sync();

        // c -> v + damped update : one warp per var
        for (int v = wid; v < NV; v += NWARP) {
            int deg = g_col_cnt[v];
            const int* __restrict__ rows = &g_col_rows[v * CD];
            float4 acc = make_float4(0.f, 0.f, 0.f, 0.f);
            for (int j = 0; j < deg; j += 4) {
                int e = j + grp;
                if (e < deg) {
                    float4 a = cT4[(rows[e] << 3) + sub];
                    acc.x += a.x; acc.y += a.y; acc.z += a.z; acc.w += a.w;
                }
            }
            #pragma unroll
            for (int ofs = 8; ofs <= 16; ofs <<= 1) {
                acc.x += __shfl_xor_sync(0xffffffffu, acc.x, ofs);
                acc.y += __shfl_xor_sync(0xffffffffu, acc.y, ofs);
                acc.z += __shfl_xor_sync(0xffffffffu, acc.z, ofs);
                acc.w += __shfl_xor_sync(0xffffffffu, acc.w, ofs);
            }
            if (lane < 8) {
                int idx = (v << 3) + sub;
                float4 vb = vT4[idx];
                float4 ch = llrT4[idx];
                float om = 1.0f - damp;
                vb.x = damp * vb.x + om * (ch.x + wcv * acc.x);
                vb.y = damp * vb.y + om * (ch.y + wcv * acc.y);
                vb.z = damp * vb.z + om * (ch.z + wcv * acc.z);
                vb.w = damp * vb.w + om * (ch.w + wcv * acc.w);
                vT4[idx] = vb;
            }
        }
        grid_sync();
    }

    // ---- output sigmoid(-v) in (b, v) order ----
    for (int i = tid; i < NB * NV; i += gsz) {
        int b = i >> 14, v = i & (NV - 1);
        float x = g_vT[(v << 5) + b];
        out[i] = 1.0f / (1.0f + expf(x));
    }
}

extern "C" void kernel_launch(void* const* d_in, const int* in_sizes, int n_in,
                              void* d_out, int out_size) {
    const float* synd = (const float*)d_in[0];
    const float* H    = (const float*)d_in[1];
    const float* llr  = (const float*)d_in[2];
    const float* wvc  = (const float*)d_in[3];
    const float* wcv  = (const float*)d_in[4];
    const float* damp = (const float*)d_in[5];
    float* out = (float*)d_out;

    k_zero<<<(NV + 255) / 256, 256>>>();
    k_build<<<B_BLOCKS, B_THREADS>>>((const uint4*)H);
    bp_persist<<<NBLK, NTHR>>>(synd, llr, wvc, wcv, damp, out);
}

// round 7
// speedup vs baseline: 1.3286x; 1.1426x over previous
#include <cuda_runtime.h>

// NeuralBPDecoder: sparse BP, 3 launches.
// k_init:    zero degree counters + transpose inputs to node-major.
// k_build:   stream H (537 MB, batched uint4 loads) -> ELL adjacency (atomics).
// bp_persist: sort lists (local-mem staging, determinism) -> 15x two-phase BP
//             with software grid barrier -> sigmoid output.
// Iteration gathers: warp per node; adjacency indices preloaded into registers
// and shfl-broadcast, so the L2 gathers are independent (deep MLP).

#define NC 8192
#define NV 16384
#define NB 32
#define RD 64
#define CD 48
#define ITERS 15
#define NBLK 148
#define NTHR 1024
#define NWARP ((NBLK * NTHR) / 32)

#define B_BLOCKS 2048
#define B_THREADS 256
#define U 8

__device__ int   g_row_cnt[NC];
__device__ int   g_row_cols[NC * RD];
__device__ int   g_col_cnt[NV];
__device__ int   g_col_rows[NV * CD];
__device__ float g_vT[NV * NB];
__device__ float g_cT[NC * NB];
__device__ float g_sT[NC * NB];
__device__ float g_llrT[NV * NB];

__device__ unsigned g_bar_arrive;
__device__ unsigned g_bar_gen;

__device__ __forceinline__ void grid_sync() {
    __syncthreads();
    if (threadIdx.x == 0) {
        __threadfence();
        volatile unsigned* genp = &g_bar_gen;
        unsigned gen = *genp;
        if (atomicAdd(&g_bar_arrive, 1) == NBLK - 1) {
            g_bar_arrive = 0;
            __threadfence();
            atomicAdd(&g_bar_gen, 1);
        } else {
            while (*genp == gen) { }
        }
        __threadfence();
    }
    __syncthreads();
}

// Zero counters + transpose inputs (independent of adjacency).
__global__ void __launch_bounds__(B_THREADS)
k_init(const float* __restrict__ synd, const float* __restrict__ llr) {
    int i = blockIdx.x * B_THREADS + threadIdx.x;
    int gsz = B_BLOCKS * B_THREADS;
    for (int t = i; t < NV; t += gsz) {
        g_col_cnt[t] = 0;
        if (t < NC) g_row_cnt[t] = 0;
    }
    for (int t = i; t < NV * NB; t += gsz) {
        int v = t >> 5, b = t & 31;
        float x = llr[b * NV + v];
        g_llrT[t] = x;
        g_vT[t]   = x;
    }
    for (int t = i; t < NC * NB; t += gsz) {
        int c = t >> 5, b = t & 31;
        g_sT[t] = 1.0f - 2.0f * synd[b * NC + c];
    }
}

__device__ __forceinline__ void emit_quad(long i, uint4 h) {
    long base = i * 4;
    unsigned vals[4] = {h.x, h.y, h.z, h.w};
    #pragma unroll
    for (int k = 0; k < 4; k++) {
        if (vals[k]) {
            long e = base + k;
            int c = (int)(e >> 14);
            int v = (int)(e & (NV - 1));
            int rs = atomicAdd(&g_row_cnt[c], 1);
            if (rs < RD) g_row_cols[c * RD + rs] = v;
            int cs = atomicAdd(&g_col_cnt[v], 1);
            if (cs < CD) g_col_rows[v * CD + cs] = c;
        }
    }
}

__global__ void __launch_bounds__(B_THREADS)
k_build(const uint4* __restrict__ H4) {
    const long n4 = (long)NC * NV / 4;
    const long stride = (long)B_BLOCKS * B_THREADS;
    long i = (long)blockIdx.x * B_THREADS + threadIdx.x;

    for (; i + (U - 1) * stride < n4; i += U * stride) {
        uint4 h[U];
        #pragma unroll
        for (int u = 0; u < U; u++)
            h[u] = __ldcs(&H4[i + u * stride]);
        #pragma unroll
        for (int u = 0; u < U; u++) {
            if (h[u].x | h[u].y | h[u].z | h[u].w)
                emit_quad(i + u * stride, h[u]);
        }
    }
    for (; i < n4; i += stride) {
        uint4 h = __ldcs(&H4[i]);
        if (h.x | h.y | h.z | h.w)
            emit_quad(i, h);
    }
}

__global__ void __launch_bounds__(NTHR, 1)
bp_persist(const float* __restrict__ wvc_p, const float* __restrict__ wcv_p,
           const float* __restrict__ damp_p, float* __restrict__ out) {
    const int tid  = blockIdx.x * NTHR + threadIdx.x;
    const int gsz  = NBLK * NTHR;
    const int wid  = tid >> 5;
    const int lane = tid & 31;
    const int sub  = lane & 7;   // float4 slot within 32-batch row
    const int grp  = lane >> 3;  // 4 simultaneous edges

    const float wvc  = __ldg(wvc_p);
    const float wcv  = __ldg(wcv_p);
    const float damp = __ldg(damp_p);

    float4* __restrict__ vT4   = (float4*)g_vT;
    float4* __restrict__ cT4   = (float4*)g_cT;
    float4* __restrict__ sT4   = (float4*)g_sT;
    float4* __restrict__ llrT4 = (float4*)g_llrT;

    // ---- sort adjacency lists (local-memory staging; deterministic order) ----
    {
        int tmp[RD];
        for (int i = tid; i < NV; i += gsz) {
            int n = min(g_col_cnt[i], CD);
            g_col_cnt[i] = n;
            int* a = &g_col_rows[i * CD];
            for (int j = 0; j < n; j++) tmp[j] = a[j];
            for (int j = 1; j < n; j++) {
                int key = tmp[j]; int k = j - 1;
                while (k >= 0 && tmp[k] > key) { tmp[k + 1] = tmp[k]; k--; }
                tmp[k + 1] = key;
            }
            for (int j = 0; j < n; j++) a[j] = tmp[j];
        }
        for (int i = tid; i < NC; i += gsz) {
            int n = min(g_row_cnt[i], RD);
            g_row_cnt[i] = n;
            int* a = &g_row_cols[i * RD];
            for (int j = 0; j < n; j++) tmp[j] = a[j];
            for (int j = 1; j < n; j++) {
                int key = tmp[j]; int k = j - 1;
                while (k >= 0 && tmp[k] > key) { tmp[k + 1] = tmp[k]; k--; }
                tmp[k + 1] = key;
            }
            for (int j = 0; j < n; j++) a[j] = tmp[j];
        }
    }
    grid_sync();

    // ---- BP iterations ----
    for (int it = 0; it < ITERS; it++) {
        // v -> c : warp per check; indices preloaded, 8 edges in flight
        for (int c = wid; c < NC; c += NWARP) {
            int deg = g_row_cnt[c];
            const int* __restrict__ cols = &g_row_cols[c * RD];
            int idxA = cols[lane];                          // one 128B load
            int idxB = (deg > 32) ? cols[32 + lane] : 0;    // rare tail
            float4 a0 = make_float4(0.f, 0.f, 0.f, 0.f);
            float4 a1 = make_float4(0.f, 0.f, 0.f, 0.f);
            for (int j = 0; j < deg; j += 8) {
                int e0 = j + grp, e1 = j + grp + 4;
                int sA0 = __shfl_sync(0xffffffffu, idxA, e0 & 31);
                int sB0 = __shfl_sync(0xffffffffu, idxB, e0 & 31);
                int sA1 = __shfl_sync(0xffffffffu, idxA, e1 & 31);
                int sB1 = __shfl_sync(0xffffffffu, idxB, e1 & 31);
                int c0 = (e0 < 32) ? sA0 : sB0;
                int c1 = (e1 < 32) ? sA1 : sB1;
                if (e0 < deg) {
                    float4 t = vT4[(c0 << 3) + sub];
                    a0.x += t.x; a0.y += t.y; a0.z += t.z; a0.w += t.w;
                }
                if (e1 < deg) {
                    float4 t = vT4[(c1 << 3) + sub];
                    a1.x += t.x; a1.y += t.y; a1.z += t.z; a1.w += t.w;
                }
            }
            float4 acc;
            acc.x = a0.x + a1.x; acc.y = a0.y + a1.y;
            acc.z = a0.z + a1.z; acc.w = a0.w + a1.w;
            #pragma unroll
            for (int ofs = 8; ofs <= 16; ofs <<= 1) {
                acc.x += __shfl_xor_sync(0xffffffffu, acc.x, ofs);
                acc.y += __shfl_xor_sync(0xffffffffu, acc.y, ofs);
                acc.z += __shfl_xor_sync(0xffffffffu, acc.z, ofs);
                acc.w += __shfl_xor_sync(0xffffffffu, acc.w, ofs);
            }
            if (lane < 8) {
                float4 s = sT4[(c << 3) + sub];
                float4 m;
                m.x = s.x * tanhf(0.5f * wvc * acc.x);
                m.y = s.y * tanhf(0.5f * wvc * acc.y);
                m.z = s.z * tanhf(0.5f * wvc * acc.z);
                m.w = s.w * tanhf(0.5f * wvc * acc.w);
                cT4[(c << 3) + sub] = m;
            }
        }
        grid_sync();

        // c -> v + damped update : warp per var
        for (int v = wid; v < NV; v += NWARP) {
            int deg = g_col_cnt[v];
            const int* __restrict__ rows = &g_col_rows[v * CD];
            int idxA = rows[lane];                               // FIXED (was rows[lane&15])
            int idxB = (deg > 32 && lane < CD - 32) ? rows[32 + lane] : 0;
            float4 a0 = make_float4(0.f, 0.f, 0.f, 0.f);
            float4 a1 = make_float4(0.f, 0.f, 0.f, 0.f);
            for (int j = 0; j < deg; j += 8) {
                int e0 = j + grp, e1 = j + grp + 4;
                int sA0 = __shfl_sync(0xffffffffu, idxA, e0 & 31);
                int sB0 = __shfl_sync(0xffffffffu, idxB, e0 & 31);
                int sA1 = __shfl_sync(0xffffffffu, idxA, e1 & 31);
                int sB1 = __shfl_sync(0xffffffffu, idxB, e1 & 31);
                int r0 = (e0 < 32) ? sA0 : sB0;
                int r1 = (e1 < 32) ? sA1 : sB1;
                if (e0 < deg) {
                    float4 t = cT4[(r0 << 3) + sub];
                    a0.x += t.x; a0.y += t.y; a0.z += t.z; a0.w += t.w;
                }
                if (e1 < deg) {
                    float4 t = cT4[(r1 << 3) + sub];
                    a1.x += t.x; a1.y += t.y; a1.z += t.z; a1.w += t.w;
                }
            }
            float4 acc;
            acc.x = a0.x + a1.x; acc.y = a0.y + a1.y;
            acc.z = a0.z + a1.z; acc.w = a0.w + a1.w;
            #pragma unroll
            for (int ofs = 8; ofs <= 16; ofs <<= 1) {
                acc.x += __shfl_xor_sync(0xffffffffu, acc.x, ofs);
                acc.y += __shfl_xor_sync(0xffffffffu, acc.y, ofs);
                acc.z += __shfl_xor_sync(0xffffffffu, acc.z, ofs);
                acc.w += __shfl_xor_sync(0xffffffffu, acc.w, ofs);
            }
            if (lane < 8) {
                int idx = (v << 3) + sub;
                float4 vb = vT4[idx];
                float4 ch = llrT4[idx];
                float om = 1.0f - damp;
                vb.x = damp * vb.x + om * (ch.x + wcv * acc.x);
                vb.y = damp * vb.y + om * (ch.y + wcv * acc.y);
                vb.z = damp * vb.z + om * (ch.z + wcv * acc.z);
                vb.w = damp * vb.w + om * (ch.w + wcv * acc.w);
                vT4[idx] = vb;
            }
        }
        grid_sync();
    }

    // ---- output sigmoid(-v) in (b, v) order ----
    for (int i = tid; i < NB * NV; i += gsz) {
        int b = i >> 14, v = i & (NV - 1);
        float x = g_vT[(v << 5) + b];
        out[i] = 1.0f / (1.0f + expf(x));
    }
}

extern "C" void kernel_launch(void* const* d_in, const int* in_sizes, int n_in,
                              void* d_out, int out_size) {
    const float* synd = (const float*)d_in[0];
    const float* H    = (const float*)d_in[1];
    const float* llr  = (const float*)d_in[2];
    const float* wvc  = (const float*)d_in[3];
    const float* wcv  = (const float*)d_in[4];
    const float* damp = (const float*)d_in[5];
    float* out = (float*)d_out;

    k_init<<<B_BLOCKS, B_THREADS>>>(synd, llr);
    k_build<<<B_BLOCKS, B_THREADS>>>((const uint4*)H);
    bp_persist<<<NBLK, NTHR>>>(wvc, wcv, damp, out);
}

// round 8
// speedup vs baseline: 1.5863x; 1.1940x over previous
#include <cuda_runtime.h>

// NeuralBPDecoder: sparse BP, 2 launches.
// k_build: stream H (537 MB, 8-deep uint4 batches) -> ELL adjacency (atomics).
//          Counters are zero at entry: static-init on call 1, re-zeroed by
//          bp_persist's epilogue on every call thereafter (graph-deterministic).
// bp_persist (148x512, co-resident, software grid barrier):
//   sort lists (determinism) -> hoist indices/degrees/signs/llrs/beliefs into
//   registers -> 15x two phases -> sigmoid output from registers.
// Layout: warp = 4 groups x 8 lanes; group owns a node; lane owns a float4
// batch-quad. Gathers are 16B/lane of a 128B node row; no reductions needed.

#define NC 8192
#define NV 16384
#define NB 32
#define RD 64
#define CD 48
#define ITERS 15
#define NBLK 148
#define NTHR 512
#define NWARP ((NBLK * NTHR) / 32)      // 2368
#define NODES_PER_ROUND (NWARP * 4)     // 9472

#define B_BLOCKS 2048
#define B_THREADS 256
#define U 8
#define FULL 0xffffffffu

__device__ int   g_row_cnt[NC];
__device__ int   g_row_cols[NC * RD];
__device__ int   g_col_cnt[NV];
__device__ int   g_col_rows[NV * CD];
__device__ float g_vT[NV * NB];         // beliefs mailbox, (v, b)
__device__ float g_cT[NC * NB];         // check messages, (c, b)

__device__ unsigned g_bar_arrive;
__device__ unsigned g_bar_gen;

__device__ __forceinline__ void grid_sync() {
    __syncthreads();
    if (threadIdx.x == 0) {
        __threadfence();
        volatile unsigned* genp = &g_bar_gen;
        unsigned gen = *genp;
        if (atomicAdd(&g_bar_arrive, 1) == NBLK - 1) {
            g_bar_arrive = 0;
            __threadfence();
            atomicAdd(&g_bar_gen, 1);
        } else {
            while (*genp == gen) { }
        }
        __threadfence();
    }
    __syncthreads();
}

__device__ __forceinline__ void emit_quad(long i, uint4 h) {
    long base = i * 4;
    unsigned vals[4] = {h.x, h.y, h.z, h.w};
    #pragma unroll
    for (int k = 0; k < 4; k++) {
        if (vals[k]) {
            long e = base + k;
            int c = (int)(e >> 14);
            int v = (int)(e & (NV - 1));
            int rs = atomicAdd(&g_row_cnt[c], 1);
            if (rs < RD) g_row_cols[c * RD + rs] = v;
            int cs = atomicAdd(&g_col_cnt[v], 1);
            if (cs < CD) g_col_rows[v * CD + cs] = c;
        }
    }
}

__global__ void __launch_bounds__(B_THREADS)
k_build(const uint4* __restrict__ H4) {
    const long n4 = (long)NC * NV / 4;
    const long stride = (long)B_BLOCKS * B_THREADS;
    long i = (long)blockIdx.x * B_THREADS + threadIdx.x;

    for (; i + (U - 1) * stride < n4; i += U * stride) {
        uint4 h[U];
        #pragma unroll
        for (int u = 0; u < U; u++)
            h[u] = __ldcs(&H4[i + u * stride]);
        #pragma unroll
        for (int u = 0; u < U; u++) {
            if (h[u].x | h[u].y | h[u].z | h[u].w)
                emit_quad(i + u * stride, h[u]);
        }
    }
    for (; i < n4; i += stride) {
        uint4 h = __ldcs(&H4[i]);
        if (h.x | h.y | h.z | h.w)
            emit_quad(i, h);
    }
}

__global__ void __launch_bounds__(NTHR, 1)
bp_persist(const float* __restrict__ synd, const float* __restrict__ llr,
           const float* __restrict__ wvc_p, const float* __restrict__ wcv_p,
           const float* __restrict__ damp_p, float* __restrict__ out) {
    const int tid   = blockIdx.x * NTHR + threadIdx.x;
    const int gsz   = NBLK * NTHR;
    const int wid   = tid >> 5;
    const int lane  = tid & 31;
    const int sub   = lane & 7;    // float4 slot (batch quad)
    const int gbase = lane & 24;   // group base lane (g << 3)

    const float wvc  = __ldg(wvc_p);
    const float wcv  = __ldg(wcv_p);
    const float damp = __ldg(damp_p);
    const float omd  = 1.0f - damp;

    float4* __restrict__ vT4 = (float4*)g_vT;
    float4* __restrict__ cT4 = (float4*)g_cT;

    // ---- sort adjacency lists (local staging; deterministic order) ----
    {
        int tmp[RD];
        for (int i = tid; i < NV; i += gsz) {
            int n = min(g_col_cnt[i], CD);
            g_col_cnt[i] = n;
            int* a = &g_col_rows[i * CD];
            for (int j = 0; j < n; j++) tmp[j] = a[j];
            for (int j = 1; j < n; j++) {
                int key = tmp[j]; int k = j - 1;
                while (k >= 0 && tmp[k] > key) { tmp[k + 1] = tmp[k]; k--; }
                tmp[k + 1] = key;
            }
            for (int j = 0; j < n; j++) a[j] = tmp[j];
        }
        for (int i = tid; i < NC; i += gsz) {
            int n = min(g_row_cnt[i], RD);
            g_row_cnt[i] = n;
            int* a = &g_row_cols[i * RD];
            for (int j = 0; j < n; j++) tmp[j] = a[j];
            for (int j = 1; j < n; j++) {
                int key = tmp[j]; int k = j - 1;
                while (k >= 0 && tmp[k] > key) { tmp[k + 1] = tmp[k]; k--; }
                tmp[k + 1] = key;
            }
            for (int j = 0; j < n; j++) a[j] = tmp[j];
        }
    }
    grid_sync();

    // ---- hoist per-node state into registers ----
    const int c = wid * 4 + (lane >> 3);       // this lane's check
    const bool chas = (c < NC);                // warp-uniform
    int cdeg = 0, cidx0 = 0, cidx1 = 0, cidx2 = 0, cidx3 = 0;
    float4 csgn = make_float4(0.f, 0.f, 0.f, 0.f);
    if (chas) {
        cdeg  = g_row_cnt[c];
        cidx0 = g_row_cols[c * RD + 0 * 8 + sub];
        cidx1 = g_row_cols[c * RD + 1 * 8 + sub];
        cidx2 = g_row_cols[c * RD + 2 * 8 + sub];
        cidx3 = g_row_cols[c * RD + 3 * 8 + sub];
        csgn.x = 1.0f - 2.0f * synd[(sub * 4 + 0) * NC + c];
        csgn.y = 1.0f - 2.0f * synd[(sub * 4 + 1) * NC + c];
        csgn.z = 1.0f - 2.0f * synd[(sub * 4 + 2) * NC + c];
        csgn.w = 1.0f - 2.0f * synd[(sub * 4 + 3) * NC + c];
    }
    int    vv[2];
    bool   vhas[2];
    int    vdeg[2];
    int    vidx[2][4];
    float4 vch[2], vb[2];
    #pragma unroll
    for (int r = 0; r < 2; r++) {
        int v = wid * 4 + (lane >> 3) + r * NODES_PER_ROUND;
        vv[r]   = v;
        vhas[r] = (v < NV);                    // warp-uniform
        vdeg[r] = 0;
        vidx[r][0] = vidx[r][1] = vidx[r][2] = vidx[r][3] = 0;
        if (vhas[r]) {
            vdeg[r]    = g_col_cnt[v];
            vidx[r][0] = g_col_rows[v * CD + 0 * 8 + sub];
            vidx[r][1] = g_col_rows[v * CD + 1 * 8 + sub];
            vidx[r][2] = g_col_rows[v * CD + 2 * 8 + sub];
            vidx[r][3] = g_col_rows[v * CD + 3 * 8 + sub];
            vch[r].x = llr[(sub * 4 + 0) * NV + v];
            vch[r].y = llr[(sub * 4 + 1) * NV + v];
            vch[r].z = llr[(sub * 4 + 2) * NV + v];
            vch[r].w = llr[(sub * 4 + 3) * NV + v];
            vb[r] = vch[r];
            vT4[(v << 3) + sub] = vb[r];       // publish initial beliefs
        }
    }
    grid_sync();

    // ---- BP iterations ----
    for (int it = 0; it < ITERS; it++) {
        // v -> c : each lane sums its batch-quad over its check's edges
        if (chas) {
            float4 acc = make_float4(0.f, 0.f, 0.f, 0.f);
            #pragma unroll
            for (int jb = 0; jb < 4; jb++) {
                int reg = (jb == 0) ? cidx0 : (jb == 1) ? cidx1
                        : (jb == 2) ? cidx2 : cidx3;
                if (__any_sync(FULL, cdeg > jb * 8)) {
                    #pragma unroll
                    for (int m = 0; m < 8; m++) {
                        int idx = __shfl_sync(FULL, reg, gbase + m);
                        if (jb * 8 + m < cdeg) {
                            float4 t = vT4[(idx << 3) + sub];
                            acc.x += t.x; acc.y += t.y;
                            acc.z += t.z; acc.w += t.w;
                        }
                    }
                }
            }
            for (int j = 32; j < cdeg; j++) {          // rare tail
                int idx = g_row_cols[c * RD + j];
                float4 t = vT4[(idx << 3) + sub];
                acc.x += t.x; acc.y += t.y; acc.z += t.z; acc.w += t.w;
            }
            float4 m4;
            m4.x = csgn.x * tanhf(0.5f * wvc * acc.x);
            m4.y = csgn.y * tanhf(0.5f * wvc * acc.y);
            m4.z = csgn.z * tanhf(0.5f * wvc * acc.z);
            m4.w = csgn.w * tanhf(0.5f * wvc * acc.w);
            cT4[(c << 3) + sub] = m4;
        }
        grid_sync();

        // c -> v + damped update
        #pragma unroll
        for (int r = 0; r < 2; r++) {
            if (vhas[r]) {
                float4 acc = make_float4(0.f, 0.f, 0.f, 0.f);
                #pragma unroll
                for (int jb = 0; jb < 4; jb++) {
                    int reg = vidx[r][jb];
                    if (__any_sync(FULL, vdeg[r] > jb * 8)) {
                        #pragma unroll
                        for (int m = 0; m < 8; m++) {
                            int idx = __shfl_sync(FULL, reg, gbase + m);
                            if (jb * 8 + m < vdeg[r]) {
                                float4 t = cT4[(idx << 3) + sub];
                                acc.x += t.x; acc.y += t.y;
                                acc.z += t.z; acc.w += t.w;
                            }
                        }
                    }
                }
                for (int j = 32; j < vdeg[r]; j++) {   // essentially never
                    int idx = g_col_rows[vv[r] * CD + j];
                    float4 t = cT4[(idx << 3) + sub];
                    acc.x += t.x; acc.y += t.y; acc.z += t.z; acc.w += t.w;
                }
                vb[r].x = damp * vb[r].x + omd * (vch[r].x + wcv * acc.x);
                vb[r].y = damp * vb[r].y + omd * (vch[r].y + wcv * acc.y);
                vb[r].z = damp * vb[r].z + omd * (vch[r].z + wcv * acc.z);
                vb[r].w = damp * vb[r].w + omd * (vch[r].w + wcv * acc.w);
                vT4[(vv[r] << 3) + sub] = vb[r];
            }
        }
        grid_sync();
    }

    // ---- output sigmoid(-v) straight from registers ----
    #pragma unroll
    for (int r = 0; r < 2; r++) {
        if (vhas[r]) {
            int v = vv[r];
            out[(sub * 4 + 0) * NV + v] = 1.0f / (1.0f + expf(vb[r].x));
            out[(sub * 4 + 1) * NV + v] = 1.0f / (1.0f + expf(vb[r].y));
            out[(sub * 4 + 2) * NV + v] = 1.0f / (1.0f + expf(vb[r].z));
            out[(sub * 4 + 3) * NV + v] = 1.0f / (1.0f + expf(vb[r].w));
        }
    }

    // ---- re-zero degree counters for the next call's k_build ----
    for (int i = tid; i < NV; i += gsz) {
        g_col_cnt[i] = 0;
        if (i < NC) g_row_cnt[i] = 0;
    }
}

extern "C" void kernel_launch(void* const* d_in, const int* in_sizes, int n_in,
                              void* d_out, int out_size) {
    const float* synd = (const float*)d_in[0];
    const float* H    = (const float*)d_in[1];
    const float* llr  = (const float*)d_in[2];
    const float* wvc  = (const float*)d_in[3];
    const float* wcv  = (const float*)d_in[4];
    const float* damp = (const float*)d_in[5];
    float* out = (float*)d_out;

    k_build<<<B_BLOCKS, B_THREADS>>>((const uint4*)H);
    bp_persist<<<NBLK, NTHR>>>(synd, llr, wvc, wcv, damp, out);
}